// round 17
// baseline (speedup 1.0000x reference)
#include <cuda_runtime.h>
#include <cuda_fp16.h>
#include <cstddef>
#include <cstdint>

#define NN0 50000
#define NN1 20000
#define NN2 8000
#define NN3 3200
#define NN4 1300

// ---------------- device scratch (no allocation allowed) ----------------
__device__ float g_x0[NN0 * 32];
__device__ float g_x1[NN1 * 32];
__device__ float g_x2[NN2 * 64];
__device__ float g_x3[NN3 * 128];
__device__ float g_x4[NN4 * 256];
__device__ float g_y [NN0 * 128];
__device__ float g_ta[NN0 * 128];
__device__ float g_tb[NN0 * 128];
__device__ float g_split[4 * 1024 * 1024];
__device__ float g_p1[800 * 512];
__device__ float g_p2[800 * 512];
__device__ float g_mean[2 * 512];
__device__ float g_istd[2 * 512];
__device__ int   g_bnctr;

// ---------------- fp16 hi/lo helpers --------------------------------------
__device__ __forceinline__ void split2(float x0, float x1, uint32_t& h, uint32_t& l)
{
    __half2 hh = __floats2half2_rn(x0, x1);
    float r0 = x0 - __low2float(hh);
    float r1 = x1 - __high2float(hh);
    __half2 ll = __floats2half2_rn(r0, r1);
    h = *reinterpret_cast<uint32_t*>(&hh);
    l = *reinterpret_cast<uint32_t*>(&ll);
}

__device__ __forceinline__ void mma_f16(float* c, const uint32_t* a, const uint32_t* b)
{
    asm volatile(
        "mma.sync.aligned.m16n8k16.row.col.f32.f16.f16.f32 "
        "{%0,%1,%2,%3}, {%4,%5,%6,%7}, {%8,%9}, {%0,%1,%2,%3};\n"
        : "+f"(c[0]), "+f"(c[1]), "+f"(c[2]), "+f"(c[3])
        : "r"(a[0]), "r"(a[1]), "r"(a[2]), "r"(a[3]),
          "r"(b[0]), "r"(b[1]));
}

// ---------------- FP16x3 tensor-core gather-GEMM (BK=32, smem pre-split) ---
// IDENTICAL to the round-16 best kernel (protected).
template<int TBM, int TBN>
__global__ __launch_bounds__(256)
void gmma_t(const float* __restrict__ X,
            const int*   __restrict__ nbr,
            const float* __restrict__ W,
            const float* __restrict__ bias,
            float* __restrict__ out,
            int M, int Cin, int Cout, int Koff, int k0, int k1, int doRelu)
{
    constexpr int BKC = 32;
    constexpr int PAh = BKC + 8;
    constexpr int PBn = TBN + 8;
    constexpr int WN  = (TBM >= 128) ? 1 : 2;
    constexpr int NF  = TBN / (8 * WN);
    constexpr int AV  = TBM / 32;
    constexpr int BT  = 4 * TBN;
    constexpr int BV  = (BT + 255) / 256;

    extern __shared__ char smB[];
    __half*   AsH = reinterpret_cast<__half*>(smB);
    __half*   AsL = AsH + 2 * TBM * PAh;
    uint32_t* BsH = reinterpret_cast<uint32_t*>(AsL + 2 * TBM * PAh);
    uint32_t* BsL = BsH + 2 * 16 * PBn;
    int*      rows = reinterpret_cast<int*>(BsL + 2 * 16 * PBn);

    const int tid  = threadIdx.x;
    const int m0   = blockIdx.y * TBM;
    const int n0   = blockIdx.x * TBN;
    const int warp = tid >> 5, lane = tid & 31;
    const int wm = warp / WN, wn = warp % WN;
    const int lg = lane >> 2, lt = lane & 3;

    const int nk      = k1 - k0;
    const int kchunks = (Cin + BKC - 1) / BKC;
    const int nIter   = nk * kchunks;
    const bool bVec = (Cout % 4 == 0) && ((((uintptr_t)W) & 15u) == 0u)
                      && (((Cin * Cout) & 3) == 0);

    for (int idx = tid; idx < nk * TBM; idx += 256) {
        int kk = idx / TBM, mi = idx - kk * TBM;
        int m  = m0 + mi;
        rows[kk * TBM + mi] = (m < M) ? (nbr ? nbr[(size_t)m * Koff + k0 + kk] : m) : 0;
    }
    __syncthreads();

    float acc[NF][4];
    #pragma unroll
    for (int f = 0; f < NF; ++f)
        #pragma unroll
        for (int j = 0; j < 4; ++j) acc[f][j] = 0.f;

    float4 aR[AV];
    float4 bR0[BV], bR1[BV];

    auto loadStage = [&](int t) {
        int k   = t / kchunks;
        int cc  = t - k * kchunks;
        int ci0 = cc * BKC;
        #pragma unroll
        for (int v = 0; v < AV; ++v) {
            int task = tid + v * 256;
            int mi = task >> 3;
            int cg = (task & 7) << 2;
            int c  = ci0 + cg;
            float4 val = make_float4(0.f, 0.f, 0.f, 0.f);
            if (c < Cin)
                val = *reinterpret_cast<const float4*>(
                          X + (size_t)rows[k * TBM + mi] * Cin + c);
            aR[v] = val;
        }
        const float* Wk = W + (size_t)(k0 + k) * Cin * Cout;
        #pragma unroll
        for (int v = 0; v < BV; ++v) {
            int task = tid + v * 256;
            float4 v0 = make_float4(0.f, 0.f, 0.f, 0.f);
            float4 v1 = v0;
            if (task < BT) {
                int kp = task / (TBN / 4);
                int ni = (task % (TBN / 4)) * 4;
                int c0 = ci0 + 2 * kp;
                int n  = n0 + ni;
                if (bVec) {
                    if (c0 < Cin && n < Cout) {
                        v0 = *reinterpret_cast<const float4*>(Wk + (size_t)c0 * Cout + n);
                        if (c0 + 1 < Cin)
                            v1 = *reinterpret_cast<const float4*>(Wk + (size_t)(c0 + 1) * Cout + n);
                    }
                } else {
                    if (c0 < Cin) {
                        const float* p = Wk + (size_t)c0 * Cout;
                        if (n + 0 < Cout) v0.x = p[n + 0];
                        if (n + 1 < Cout) v0.y = p[n + 1];
                        if (n + 2 < Cout) v0.z = p[n + 2];
                        if (n + 3 < Cout) v0.w = p[n + 3];
                    }
                    if (c0 + 1 < Cin) {
                        const float* p = Wk + (size_t)(c0 + 1) * Cout;
                        if (n + 0 < Cout) v1.x = p[n + 0];
                        if (n + 1 < Cout) v1.y = p[n + 1];
                        if (n + 2 < Cout) v1.z = p[n + 2];
                        if (n + 3 < Cout) v1.w = p[n + 3];
                    }
                }
            }
            bR0[v] = v0;
            bR1[v] = v1;
        }
    };

    auto storeStage = [&](int s) {
        #pragma unroll
        for (int v = 0; v < AV; ++v) {
            int task = tid + v * 256;
            int mi = task >> 3;
            int cg = (task & 7) << 2;
            uint32_t h0, l0, h1, l1;
            split2(aR[v].x, aR[v].y, h0, l0);
            split2(aR[v].z, aR[v].w, h1, l1);
            int off = (s * TBM + mi) * PAh + cg;
            *reinterpret_cast<uint2*>(AsH + off) = make_uint2(h0, h1);
            *reinterpret_cast<uint2*>(AsL + off) = make_uint2(l0, l1);
        }
        #pragma unroll
        for (int v = 0; v < BV; ++v) {
            int task = tid + v * 256;
            if (task < BT) {
                int kp = task / (TBN / 4);
                int ni = (task % (TBN / 4)) * 4;
                uint32_t h[4], l[4];
                split2(bR0[v].x, bR1[v].x, h[0], l[0]);
                split2(bR0[v].y, bR1[v].y, h[1], l[1]);
                split2(bR0[v].z, bR1[v].z, h[2], l[2]);
                split2(bR0[v].w, bR1[v].w, h[3], l[3]);
                int off = (s * 16 + kp) * PBn + ni;
                *reinterpret_cast<uint4*>(BsH + off) = make_uint4(h[0], h[1], h[2], h[3]);
                *reinterpret_cast<uint4*>(BsL + off) = make_uint4(l[0], l[1], l[2], l[3]);
            }
        }
    };

    auto computeStage = [&](int s) {
        #pragma unroll
        for (int ks = 0; ks < 2; ++ks) {
            const int cb = ks * 16;
            const __half* aH = AsH + (s * TBM) * PAh;
            const __half* aL = AsL + (s * TBM) * PAh;
            const int mA = wm * 16 + lg;
            const int cA = cb + 2 * lt;
            uint32_t ah[4], al[4];
            ah[0] = *reinterpret_cast<const uint32_t*>(aH + (mA    ) * PAh + cA    );
            ah[1] = *reinterpret_cast<const uint32_t*>(aH + (mA + 8) * PAh + cA    );
            ah[2] = *reinterpret_cast<const uint32_t*>(aH + (mA    ) * PAh + cA + 8);
            ah[3] = *reinterpret_cast<const uint32_t*>(aH + (mA + 8) * PAh + cA + 8);
            al[0] = *reinterpret_cast<const uint32_t*>(aL + (mA    ) * PAh + cA    );
            al[1] = *reinterpret_cast<const uint32_t*>(aL + (mA + 8) * PAh + cA    );
            al[2] = *reinterpret_cast<const uint32_t*>(aL + (mA    ) * PAh + cA + 8);
            al[3] = *reinterpret_cast<const uint32_t*>(aL + (mA + 8) * PAh + cA + 8);
            const uint32_t* bHp = BsH + (s * 16 + ks * 8) * PBn;
            const uint32_t* bLp = BsL + (s * 16 + ks * 8) * PBn;
            #pragma unroll
            for (int f = 0; f < NF; ++f) {
                const int nB = wn * (TBN / WN) + f * 8 + lg;
                uint32_t bh[2], bl[2];
                bh[0] = bHp[(lt    ) * PBn + nB];
                bh[1] = bHp[(lt + 4) * PBn + nB];
                bl[0] = bLp[(lt    ) * PBn + nB];
                bl[1] = bLp[(lt + 4) * PBn + nB];
                mma_f16(acc[f], al, bh);
                mma_f16(acc[f], ah, bl);
                mma_f16(acc[f], ah, bh);
            }
        }
    };

    loadStage(0);
    storeStage(0);
    __syncthreads();

    for (int t = 0; t < nIter; ++t) {
        int cur = t & 1;
        if (t + 1 < nIter) loadStage(t + 1);
        computeStage(cur);
        if (t + 1 < nIter) storeStage(cur ^ 1);
        __syncthreads();
    }

    #pragma unroll
    for (int f = 0; f < NF; ++f) {
        int nb  = n0 + wn * (TBN / WN) + f * 8;
        int c0i = nb + lt * 2;
        int r   = m0 + wm * 16 + lg;
        float b0v = 0.f, b1v = 0.f;
        if (bias) {
            if (c0i     < Cout) b0v = bias[c0i];
            if (c0i + 1 < Cout) b1v = bias[c0i + 1];
        }
        if (r < M) {
            if (c0i < Cout) {
                float v = acc[f][0] + b0v;
                if (doRelu) v = fmaxf(v, 0.f);
                out[(size_t)r * Cout + c0i] = v;
            }
            if (c0i + 1 < Cout) {
                float v = acc[f][1] + b1v;
                if (doRelu) v = fmaxf(v, 0.f);
                out[(size_t)r * Cout + c0i + 1] = v;
            }
        }
        int r2 = r + 8;
        if (r2 < M) {
            if (c0i < Cout) {
                float v = acc[f][2] + b0v;
                if (doRelu) v = fmaxf(v, 0.f);
                out[(size_t)r2 * Cout + c0i] = v;
            }
            if (c0i + 1 < Cout) {
                float v = acc[f][3] + b1v;
                if (doRelu) v = fmaxf(v, 0.f);
                out[(size_t)r2 * Cout + c0i + 1] = v;
            }
        }
    }
}

// ordered deterministic sum of S split partials
__global__ void reduce_split_kernel(const float* __restrict__ buf,
                                    float* __restrict__ out,
                                    long long MN, int S)
{
    long long i = (long long)blockIdx.x * blockDim.x + threadIdx.x;
    if (i >= MN) return;
    float s = 0.f;
    for (int k = 0; k < S; ++k) s += buf[(size_t)k * MN + i];
    out[i] = s;
}

// ---------------- fused BN stats + finalize (single launch) ----------------
// Each block writes per-block column partials; the last-arriving block
// performs the finalize in fixed order (deterministic).
#define STAT_ROWS 256
__global__ void bn_stats_fused(const float* __restrict__ x, int M, int C,
                               float* __restrict__ p1, float* __restrict__ p2,
                               float* __restrict__ mean, float* __restrict__ istd)
{
    const int nblk = gridDim.x;
    const int r0   = blockIdx.x * STAT_ROWS;
    const int rend = min(r0 + STAT_ROWS, M);
    const int c0 = threadIdx.x;
    const int c1 = threadIdx.x + 256;
    float a0 = 0.f, q0 = 0.f, a1 = 0.f, q1 = 0.f;
    for (int r = r0; r < rend; ++r) {
        const float* row = x + (size_t)r * C;
        if (c0 < C) { float v = row[c0]; a0 += v; q0 += v * v; }
        if (c1 < C) { float v = row[c1]; a1 += v; q1 += v * v; }
    }
    float* o1 = p1 + (size_t)blockIdx.x * 512;
    float* o2 = p2 + (size_t)blockIdx.x * 512;
    if (c0 < C) { o1[c0] = a0; o2[c0] = q0; }
    if (c1 < C) { o1[c1] = a1; o2[c1] = q1; }

    __threadfence();
    __shared__ int last;
    if (threadIdx.x == 0) {
        int prev = atomicAdd(&g_bnctr, 1);
        last = (prev == nblk - 1) ? 1 : 0;
        if (last) g_bnctr = 0;                 // reset for next call / graph replay
    }
    __syncthreads();
    if (!last) return;

    for (int c = threadIdx.x; c < C; c += 256) {
        float s1 = 0.f, s2 = 0.f;
        for (int b = 0; b < nblk; ++b) {
            s1 += p1[(size_t)b * 512 + c];
            s2 += p2[(size_t)b * 512 + c];
        }
        float m = s1 / (float)M;
        float v = s2 / (float)M - m * m;
        mean[c] = m;
        istd[c] = rsqrtf(v + 1e-5f);
    }
}

// float4-vectorized BN apply with output stride (C % 4 == 0 always)
// mode 0: relu(bn(a)); 1: relu(bn(a)+b); 2: relu(bn(a)+bn2(b))
__global__ void bn_apply_kernel(const float* __restrict__ a,
                                const float* __restrict__ b,
                                const float* __restrict__ m0, const float* __restrict__ i0,
                                const float* __restrict__ m1, const float* __restrict__ i1,
                                float* __restrict__ out, int M, int C, int mode, int ostride)
{
    size_t i = (size_t)blockIdx.x * blockDim.x + threadIdx.x;
    int C4 = C >> 2;
    size_t total4 = (size_t)M * C4;
    if (i >= total4) return;
    int r = (int)(i / (size_t)C4);
    int c = (int)(i % (size_t)C4) << 2;
    float4 va = reinterpret_cast<const float4*>(a)[i];
    float4 rr;
    rr.x = (va.x - m0[c + 0]) * i0[c + 0];
    rr.y = (va.y - m0[c + 1]) * i0[c + 1];
    rr.z = (va.z - m0[c + 2]) * i0[c + 2];
    rr.w = (va.w - m0[c + 3]) * i0[c + 3];
    if (mode == 1) {
        float4 vb = reinterpret_cast<const float4*>(b)[i];
        rr.x += vb.x; rr.y += vb.y; rr.z += vb.z; rr.w += vb.w;
    } else if (mode == 2) {
        float4 vb = reinterpret_cast<const float4*>(b)[i];
        rr.x += (vb.x - m1[c + 0]) * i1[c + 0];
        rr.y += (vb.y - m1[c + 1]) * i1[c + 1];
        rr.z += (vb.z - m1[c + 2]) * i1[c + 2];
        rr.w += (vb.w - m1[c + 3]) * i1[c + 3];
    }
    rr.x = fmaxf(rr.x, 0.f); rr.y = fmaxf(rr.y, 0.f);
    rr.z = fmaxf(rr.z, 0.f); rr.w = fmaxf(rr.w, 0.f);
    *reinterpret_cast<float4*>(out + (size_t)r * ostride + c) = rr;
}

// ---------------- transposed conv: 4 rows per block (warp-per-row) --------
__global__ void deconv_kernel(const float* __restrict__ X,
                              const int* __restrict__ parent,
                              const int* __restrict__ koff,
                              const float* __restrict__ W,
                              float* __restrict__ out,
                              int M, int Cin, int Cout)
{
    __shared__ float xs[4][256];
    const int warp = threadIdx.x >> 5;
    const int lane = threadIdx.x & 31;
    const int m = blockIdx.x * 4 + warp;
    if (m >= M) return;
    const int p = parent[m];
    const int o = koff[m];
    for (int c = lane; c < Cin; c += 32)
        xs[warp][c] = X[(size_t)p * Cin + c];
    __syncwarp();
    const float* Wk = W + (size_t)o * Cin * Cout;
    for (int n = lane; n < Cout; n += 32) {
        float acc = 0.f;
        #pragma unroll 4
        for (int ci = 0; ci < Cin; ++ci)
            acc += xs[warp][ci] * Wk[(size_t)ci * Cout + n];
        out[(size_t)m * Cout + n] = acc;
    }
}

// copy skip columns into strided concat output (all C % 4 == 0)
__global__ void copy_skip_kernel(const float* __restrict__ skip,
                                 float* __restrict__ out,
                                 int M, int Cb, int Ca, int Cstride)
{
    size_t i = (size_t)blockIdx.x * blockDim.x + threadIdx.x;
    int C4 = Cb >> 2;
    size_t total4 = (size_t)M * C4;
    if (i >= total4) return;
    int r = (int)(i / (size_t)C4);
    int c = (int)(i % (size_t)C4) << 2;
    float4 v = *reinterpret_cast<const float4*>(skip + (size_t)r * Cb + c);
    *reinterpret_cast<float4*>(out + (size_t)r * Cstride + Ca + c) = v;
}

// ---------------- host-side orchestration --------------------------------
static float *TA, *TB, *Y, *X0, *X1, *X2, *X3, *X4, *SPL, *P1, *P2, *MEAN, *ISTD;
static const float* gP;
static size_t gOff;

static inline const float* takeP(size_t n) { const float* w = gP + gOff; gOff += n; return w; }
static inline int cdiv(int a, int b) { return (a + b - 1) / b; }

static inline size_t gmma_smem(int TBM, int TBN)
{
    int PBn = TBN + 8;
    size_t bytes = (size_t)2 * TBM * 40 * 2 * 2
                 + (size_t)2 * 16 * PBn * 4 * 2
                 + (size_t)27 * TBM * 4;
    return bytes;
}

static void launch_gmma(int TBM, int TBN, dim3 grid,
                        const float* X, const int* nbr, const float* W,
                        const float* bias, float* out,
                        int M, int Cin, int Cout, int K, int k0, int k1, int relu)
{
    size_t sh = gmma_smem(TBM, TBN);
    if (TBM == 128) {
        switch (TBN) {
        case 32: gmma_t<128, 32><<<grid, 256, sh>>>(X, nbr, W, bias, out, M, Cin, Cout, K, k0, k1, relu); break;
        case 48: gmma_t<128, 48><<<grid, 256, sh>>>(X, nbr, W, bias, out, M, Cin, Cout, K, k0, k1, relu); break;
        default: gmma_t<128, 64><<<grid, 256, sh>>>(X, nbr, W, bias, out, M, Cin, Cout, K, k0, k1, relu); break;
        }
    } else {
        switch (TBN) {
        case 32: gmma_t<64, 32><<<grid, 256, sh>>>(X, nbr, W, bias, out, M, Cin, Cout, K, k0, k1, relu); break;
        case 96: gmma_t<64, 96><<<grid, 256, sh>>>(X, nbr, W, bias, out, M, Cin, Cout, K, k0, k1, relu); break;
        default: gmma_t<64, 64><<<grid, 256, sh>>>(X, nbr, W, bias, out, M, Cin, Cout, K, k0, k1, relu); break;
        }
    }
}

static void run_conv(const float* X, const int* nbr, const float* W, float* out,
                     int M, int Cin, int Cout, int K,
                     const float* bias = nullptr, int relu = 0)
{
    int TBM, TBN;
    if (Cout == 96) {
        if ((long long)cdiv(M, 128) * 2 >= 148) { TBM = 128; TBN = 48; }
        else                                    { TBM = 64;  TBN = 96; }
    } else if (Cout <= 32) {
        if (cdiv(M, 128) >= 148) { TBM = 128; TBN = 32; }
        else                     { TBM = 64;  TBN = 32; }
    } else {
        if ((long long)cdiv(M, 128) * cdiv(Cout, 64) >= 148) { TBM = 128; TBN = 64; }
        else                                                 { TBM = 64;  TBN = 64; }
    }
    dim3 grid(cdiv(Cout, TBN), cdiv(M, TBM));
    int blocks = grid.x * grid.y;

    int S = 1, kper = K;
    if (nbr && K > 1 && blocks < 296 && TBM == 64) {
        S = (296 + blocks - 1) / blocks;
        if (S > K) S = K;
        kper = (K + S - 1) / S;
        S = (K + kper - 1) / kper;
    }
    if (S == 1) {
        launch_gmma(TBM, TBN, grid, X, nbr, W, bias, out, M, Cin, Cout, K, 0, K, relu);
    } else {
        long long MN = (long long)M * Cout;
        for (int s = 0; s < S; ++s) {
            int k0 = s * kper;
            int k1 = k0 + kper; if (k1 > K) k1 = K;
            launch_gmma(TBM, TBN, grid, X, nbr, W, nullptr, SPL + (size_t)s * MN,
                        M, Cin, Cout, K, k0, k1, 0);
        }
        reduce_split_kernel<<<(unsigned)((MN + 255) / 256), 256>>>(SPL, out, MN, S);
    }
}

static void run_bn(const float* a, int M, int C, int slot)
{
    int nb = cdiv(M, STAT_ROWS);
    bn_stats_fused<<<nb, 256>>>(a, M, C, P1, P2,
                                MEAN + slot * 512, ISTD + slot * 512);
}

static void run_apply(const float* a, const float* b, float* out, int M, int C,
                      int mode, int ostride)
{
    size_t total4 = (size_t)M * (C >> 2);
    bn_apply_kernel<<<(unsigned)((total4 + 255) / 256), 256>>>(
        a, b, MEAN, ISTD, MEAN + 512, ISTD + 512, out, M, C, mode, ostride);
}

static void cbr(const float* x, const int* nbr, int M, int Cin, int Cout, int K, float* out)
{
    const float* w = takeP((size_t)K * Cin * Cout);
    run_conv(x, nbr, w, TA, M, Cin, Cout, K);
    run_bn(TA, M, Cout, 0);
    run_apply(TA, nullptr, out, M, Cout, 0, Cout);
}

static void resblock(const float* x, const int* nbr, int M, int ci, int co, float* out)
{
    const float* w1 = takeP((size_t)27 * ci * co);
    const float* w2 = takeP((size_t)27 * co * co);
    run_conv(x, nbr, w1, TA, M, ci, co, 27);
    run_bn(TA, M, co, 0);
    run_apply(TA, nullptr, TB, M, co, 0, co);
    run_conv(TB, nbr, w2, TA, M, co, co, 27);
    run_bn(TA, M, co, 0);
    if (ci != co) {
        const float* ws = takeP((size_t)ci * co);
        run_conv(x, nullptr, ws, TB, M, ci, co, 1);
        run_bn(TB, M, co, 1);
        run_apply(TA, TB, out, M, co, 2, co);
    } else {
        run_apply(TA, x, out, M, co, 1, co);
    }
}

static void up_block(const float* x, const int* par, const int* off, int M,
                     int Cin, int Cout, const float* skip, int Cskip, float* out)
{
    const float* w = takeP((size_t)8 * Cin * Cout);
    deconv_kernel<<<cdiv(M, 4), 128>>>(x, par, off, w, TA, M, Cin, Cout);
    run_bn(TA, M, Cout, 0);
    // BN+ReLU written directly into concat destination (strided)
    run_apply(TA, nullptr, out, M, Cout, 0, Cout + Cskip);
    size_t total4 = (size_t)M * (Cskip >> 2);
    copy_skip_kernel<<<(unsigned)((total4 + 255) / 256), 256>>>(
        skip, out, M, Cskip, Cout, Cout + Cskip);
}

extern "C" void kernel_launch(void* const* d_in, const int* in_sizes, int n_in,
                              void* d_out, int out_size)
{
    const float* x    = (const float*)d_in[0];
    const int* nbr0   = (const int*)d_in[1];
    const int* nbr1   = (const int*)d_in[2];
    const int* nbr2   = (const int*)d_in[3];
    const int* nbr3   = (const int*)d_in[4];
    const int* nbr4   = (const int*)d_in[5];
    const int* d1     = (const int*)d_in[6];
    const int* d2     = (const int*)d_in[7];
    const int* d3     = (const int*)d_in[8];
    const int* d4     = (const int*)d_in[9];
    const int* u1p    = (const int*)d_in[10];
    const int* u1o    = (const int*)d_in[11];
    const int* u2p    = (const int*)d_in[12];
    const int* u2o    = (const int*)d_in[13];
    const int* u3p    = (const int*)d_in[14];
    const int* u3o    = (const int*)d_in[15];
    const int* u4p    = (const int*)d_in[16];
    const int* u4o    = (const int*)d_in[17];
    gP = (const float*)d_in[18];
    gOff = 0;

    cudaFuncSetAttribute((const void*)gmma_t< 64, 32>, cudaFuncAttributeMaxDynamicSharedMemorySize, 101376);
    cudaFuncSetAttribute((const void*)gmma_t< 64, 64>, cudaFuncAttributeMaxDynamicSharedMemorySize, 101376);
    cudaFuncSetAttribute((const void*)gmma_t< 64, 96>, cudaFuncAttributeMaxDynamicSharedMemorySize, 101376);
    cudaFuncSetAttribute((const void*)gmma_t<128, 32>, cudaFuncAttributeMaxDynamicSharedMemorySize, 101376);
    cudaFuncSetAttribute((const void*)gmma_t<128, 48>, cudaFuncAttributeMaxDynamicSharedMemorySize, 101376);
    cudaFuncSetAttribute((const void*)gmma_t<128, 64>, cudaFuncAttributeMaxDynamicSharedMemorySize, 101376);

    cudaGetSymbolAddress((void**)&X0,   g_x0);
    cudaGetSymbolAddress((void**)&X1,   g_x1);
    cudaGetSymbolAddress((void**)&X2,   g_x2);
    cudaGetSymbolAddress((void**)&X3,   g_x3);
    cudaGetSymbolAddress((void**)&X4,   g_x4);
    cudaGetSymbolAddress((void**)&Y,    g_y);
    cudaGetSymbolAddress((void**)&TA,   g_ta);
    cudaGetSymbolAddress((void**)&TB,   g_tb);
    cudaGetSymbolAddress((void**)&SPL,  g_split);
    cudaGetSymbolAddress((void**)&P1,   g_p1);
    cudaGetSymbolAddress((void**)&P2,   g_p2);
    cudaGetSymbolAddress((void**)&MEAN, g_mean);
    cudaGetSymbolAddress((void**)&ISTD, g_istd);

    // ---- stem (N0) ----
    cbr(x,  nbr0, NN0, 4,  32, 27, X0);
    cbr(X0, nbr0, NN0, 32, 32, 27, X0);

    // ---- stage1 (N1) ----
    cbr(X0, d1, NN1, 32, 32, 8, Y);
    resblock(Y, nbr1, NN1, 32, 32, Y);
    resblock(Y, nbr1, NN1, 32, 32, X1);

    // ---- stage2 (N2) ----
    cbr(X1, d2, NN2, 32, 32, 8, Y);
    resblock(Y, nbr2, NN2, 32, 64, Y);
    resblock(Y, nbr2, NN2, 64, 64, X2);

    // ---- stage3 (N3) ----
    cbr(X2, d3, NN3, 64, 64, 8, Y);
    resblock(Y, nbr3, NN3, 64, 128, Y);
    resblock(Y, nbr3, NN3, 128, 128, X3);

    // ---- stage4 (N4) ----
    cbr(X3, d4, NN4, 128, 128, 8, Y);
    resblock(Y, nbr4, NN4, 128, 256, Y);
    resblock(Y, nbr4, NN4, 256, 256, X4);

    // ---- up1 (N3) ----
    up_block(X4, u1p, u1o, NN3, 256, 256, X3, 128, Y);
    resblock(Y, nbr3, NN3, 384, 256, Y);
    resblock(Y, nbr3, NN3, 256, 256, Y);

    // ---- up2 (N2) ----
    up_block(Y, u2p, u2o, NN2, 256, 128, X2, 64, Y);
    resblock(Y, nbr2, NN2, 192, 128, Y);
    resblock(Y, nbr2, NN2, 128, 128, Y);

    // ---- up3 (N1) ----
    up_block(Y, u3p, u3o, NN1, 128, 96, X1, 32, Y);
    resblock(Y, nbr1, NN1, 128, 96, Y);
    resblock(Y, nbr1, NN1, 96, 96, Y);

    // ---- up4 (N0) ----
    up_block(Y, u4p, u4o, NN0, 96, 96, X0, 32, Y);
    resblock(Y, nbr0, NN0, 128, 96, Y);
    resblock(Y, nbr0, NN0, 96, 96, Y);

    // ---- head ----
    const float* wc = takeP((size_t)96 * 19);
    const float* bc = takeP(19);
    const float* w1 = takeP((size_t)96 * 96);
    const float* b1 = takeP(96);
    const float* w2 = takeP((size_t)96 * 128);
    const float* b2 = takeP(128);

    float* out = (float*)d_out;
    run_conv(Y, nullptr, wc, out, NN0, 96, 19, 1, bc, 0);
    run_conv(Y,  nullptr, w1, TA, NN0, 96, 96, 1, b1, 1);
    run_conv(TA, nullptr, w2, out + (size_t)NN0 * 19, NN0, 96, 128, 1, b2, 0);
}